// round 1
// baseline (speedup 1.0000x reference)
#include <cuda_runtime.h>
#include <cstdint>

#define AN 200000
#define NCLS 20          // foreground classes (labels 1..20)
#define NB1 1024         // level-1 histogram bins
#define TOPK 400
#define SIDE_CAP 4096
#define SEL_CAP 512
#define DET 200
#define SCORE_T 0.01f
#define NMS_T 0.45f
#define BIN_BASE 0x3C23  // float bits of 0.01f >> 16

// ---------------- scratch (static device globals; no allocation) -------------
__device__ float              g_scores[NCLS * AN];      // masked fg scores [cls][anchor]
__device__ float              g_boxes[AN * 4];          // decoded+clipped boxes
__device__ int                g_hist1[NCLS * NB1];
__device__ int                g_cutbin[NCLS];           // -1 => select-all mode
__device__ int                g_need[NCLS];
__device__ unsigned long long g_sel[NCLS * SEL_CAP];    // (scorebits<<32)|(~idx)
__device__ int                g_selCnt[NCLS];
__device__ unsigned long long g_side[NCLS * SIDE_CAP];
__device__ int                g_sideCnt[NCLS];
__device__ int                g_nmsN[NCLS];
__device__ unsigned char      g_keep[NCLS * SEL_CAP];

__device__ __forceinline__ int bin1_of(float s) {
    int b = (int)(__float_as_uint(s) >> 16) - BIN_BASE;
    return min(max(b, 0), NB1 - 1);
}

// ---------------- K0: zero counters/histograms -------------------------------
__global__ void k_init() {
    int t = blockIdx.x * blockDim.x + threadIdx.x;
    if (t < NCLS * NB1) g_hist1[t] = 0;
    if (t < NCLS) { g_selCnt[t] = 0; g_sideCnt[t] = 0; }
}

// ---------------- K1: softmax + decode + hist --------------------------------
__global__ void k_prep(const float* __restrict__ logits,
                       const float* __restrict__ reg,
                       const float* __restrict__ anc) {
    int i = blockIdx.x * blockDim.x + threadIdx.x;
    if (i >= AN) return;

    // softmax over 21 classes
    const float* L = logits + (long)i * 21;
    float e[21];
    float m = L[0];
#pragma unroll
    for (int c = 1; c < 21; c++) m = fmaxf(m, L[c]);
    float s = 0.f;
#pragma unroll
    for (int c = 0; c < 21; c++) { e[c] = expf(L[c] - m); s += e[c]; }

#pragma unroll
    for (int c = 1; c < 21; c++) {
        float sc = e[c] / s;
        float v = (sc > SCORE_T) ? sc : -1.0f;
        g_scores[(c - 1) * AN + i] = v;
        if (sc > SCORE_T) atomicAdd(&g_hist1[(c - 1) * NB1 + bin1_of(sc)], 1);
    }

    // decode (torchvision BoxCoder, weights 10,10,5,5) + clip to 320x320
    float ax1 = anc[i * 4 + 0], ay1 = anc[i * 4 + 1];
    float ax2 = anc[i * 4 + 2], ay2 = anc[i * 4 + 3];
    float aw = ax2 - ax1, ah = ay2 - ay1;
    float acx = ax1 + 0.5f * aw, acy = ay1 + 0.5f * ah;
    float dx = reg[i * 4 + 0] / 10.0f;
    float dy = reg[i * 4 + 1] / 10.0f;
    float dw = fminf(reg[i * 4 + 2] / 5.0f, 4.135166556742356f);
    float dh = fminf(reg[i * 4 + 3] / 5.0f, 4.135166556742356f);
    float pcx = dx * aw + acx, pcy = dy * ah + acy;
    float pw = expf(dw) * aw, ph = expf(dh) * ah;
    float bx1 = pcx - 0.5f * pw, by1 = pcy - 0.5f * ph;
    float bx2 = pcx + 0.5f * pw, by2 = pcy + 0.5f * ph;
    g_boxes[i * 4 + 0] = fminf(fmaxf(bx1, 0.f), 320.f);
    g_boxes[i * 4 + 1] = fminf(fmaxf(by1, 0.f), 320.f);
    g_boxes[i * 4 + 2] = fminf(fmaxf(bx2, 0.f), 320.f);
    g_boxes[i * 4 + 3] = fminf(fmaxf(by2, 0.f), 320.f);
}

// ---------------- K2: per-class rank-400 cutoff bin --------------------------
__global__ void k_cut() {
    int c = threadIdx.x;
    if (c >= NCLS) return;
    const int* h = &g_hist1[c * NB1];
    int total = 0;
    for (int b = 0; b < NB1; b++) total += h[b];
    if (total <= TOPK) { g_cutbin[c] = -1; g_need[c] = 0; return; }
    int cum = 0;
    for (int b = NB1 - 1; b >= 0; b--) {
        int hb = h[b];
        if (cum + hb >= TOPK) { g_cutbin[c] = b; g_need[c] = TOPK - cum; return; }
        cum += hb;
    }
}

// ---------------- K3: collect definite + cutoff-bin items --------------------
__global__ void k_collect() {
    int c = blockIdx.y;
    int i = blockIdx.x * blockDim.x + threadIdx.x;
    if (i >= AN) return;
    float v = g_scores[c * AN + i];
    if (v <= SCORE_T) return;
    unsigned long long key =
        ((unsigned long long)__float_as_uint(v) << 32) | (0xFFFFFFFFu - (unsigned)i);
    int cut = g_cutbin[c];
    if (cut < 0) {
        int p = atomicAdd(&g_selCnt[c], 1);
        g_sel[c * SEL_CAP + p] = key;
        return;
    }
    int b = bin1_of(v);
    if (b > cut) {
        int p = atomicAdd(&g_selCnt[c], 1);
        g_sel[c * SEL_CAP + p] = key;
    } else if (b == cut) {
        int p = atomicAdd(&g_sideCnt[c], 1);
        if (p < SIDE_CAP) g_side[c * SIDE_CAP + p] = key;
    }
}

// ---------------- bitonic sort (descending) in shared ------------------------
__device__ void bitonic_desc(unsigned long long* buf, int np2) {
    int tid = threadIdx.x, bd = blockDim.x;
    for (int k = 2; k <= np2; k <<= 1) {
        for (int j = k >> 1; j > 0; j >>= 1) {
            for (int t = tid; t < np2; t += bd) {
                int ixj = t ^ j;
                if (ixj > t) {
                    unsigned long long a = buf[t], b = buf[ixj];
                    bool desc = ((t & k) == 0);
                    if ((a < b) == desc) { buf[t] = b; buf[ixj] = a; }
                }
            }
            __syncthreads();
        }
    }
}

// ---------------- K4: finalize per-class top-400, sort ------------------------
__global__ void k_final() {
    __shared__ unsigned long long buf[SIDE_CAP];
    int c = blockIdx.x, tid = threadIdx.x;
    int cut = g_cutbin[c];
    int total;
    if (cut >= 0) {
        int n = min(g_sideCnt[c], SIDE_CAP);
        int np2 = 2; while (np2 < n) np2 <<= 1;
        for (int t = tid; t < np2; t += blockDim.x)
            buf[t] = (t < n) ? g_side[c * SIDE_CAP + t] : 0ull;
        __syncthreads();
        bitonic_desc(buf, np2);
        int need = g_need[c]; if (need > n) need = n;
        int base = g_selCnt[c];
        for (int t = tid; t < need; t += blockDim.x) g_sel[c * SEL_CAP + base + t] = buf[t];
        total = base + need;
        __syncthreads();
    } else {
        total = g_selCnt[c];
    }
    // sort the selected list (score desc, idx asc)
    for (int t = tid; t < SEL_CAP; t += blockDim.x)
        buf[t] = (t < total) ? g_sel[c * SEL_CAP + t] : 0ull;
    __syncthreads();
    bitonic_desc(buf, SEL_CAP);
    for (int t = tid; t < SEL_CAP; t += blockDim.x) g_sel[c * SEL_CAP + t] = buf[t];
    if (tid == 0) g_nmsN[c] = total;
}

// ---------------- K5: per-class greedy NMS -----------------------------------
__global__ void k_nms() {
    __shared__ float X1[TOPK], Y1[TOPK], X2[TOPK], Y2[TOPK], AR[TOPK];
    __shared__ unsigned char kp[TOPK];
    int c = blockIdx.x, tid = threadIdx.x;
    int n = g_nmsN[c];
    for (int t = tid; t < n; t += blockDim.x) {
        unsigned long long key = g_sel[c * SEL_CAP + t];
        unsigned idx = 0xFFFFFFFFu - (unsigned)(key & 0xFFFFFFFFull);
        float x1 = g_boxes[idx * 4 + 0], y1 = g_boxes[idx * 4 + 1];
        float x2 = g_boxes[idx * 4 + 2], y2 = g_boxes[idx * 4 + 3];
        X1[t] = x1; Y1[t] = y1; X2[t] = x2; Y2[t] = y2;
        AR[t] = (x2 - x1) * (y2 - y1);
        kp[t] = 1;
    }
    __syncthreads();
    for (int i = 0; i < n - 1; i++) {
        if (kp[i]) {
            float xi1 = X1[i], yi1 = Y1[i], xi2 = X2[i], yi2 = Y2[i], ai = AR[i];
            for (int j = i + 1 + tid; j < n; j += blockDim.x) {
                if (kp[j]) {
                    float lx = fmaxf(xi1, X1[j]), ly = fmaxf(yi1, Y1[j]);
                    float rx = fminf(xi2, X2[j]), ry = fminf(yi2, Y2[j]);
                    float w = fmaxf(rx - lx, 0.f), h = fmaxf(ry - ly, 0.f);
                    float inter = w * h;
                    float iou = inter / (ai + AR[j] - inter);  // NaN>T == false, matches ref
                    if (iou > NMS_T) kp[j] = 0;
                }
            }
        }
        __syncthreads();
    }
    for (int t = tid; t < n; t += blockDim.x) g_keep[c * SEL_CAP + t] = kp[t];
}

// ---------------- K6: 20-way merge of kept lists, write top-200 --------------
__global__ void k_out(float* __restrict__ out, int out_size) {
    int lane = threadIdx.x;
    // zero entire output (harness poisons with 0xAA)
    for (int t = lane; t < out_size; t += 32) out[t] = 0.f;
    __syncwarp();
    if (out_size < 1200) return;

    int c = lane;                                   // lanes 0..19 own classes 1..20
    int cnt = (c < NCLS) ? g_nmsN[c] : 0;
    int ptr = 0;
    for (int k = 0; k < DET; k++) {
        unsigned sb = 0;
        if (c < NCLS) {
            while (ptr < cnt && !g_keep[c * SEL_CAP + ptr]) ptr++;
            if (ptr < cnt) sb = (unsigned)(g_sel[c * SEL_CAP + ptr] >> 32);
        }
        // argmax over lanes: score desc, class asc on ties (matches stable argsort)
        unsigned best = sb; int bl = lane;
        for (int off = 16; off; off >>= 1) {
            unsigned ob = __shfl_down_sync(0xffffffff, best, off);
            int      ol = __shfl_down_sync(0xffffffff, bl, off);
            if (ob > best || (ob == best && ol < bl)) { best = ob; bl = ol; }
        }
        best = __shfl_sync(0xffffffff, best, 0);
        bl   = __shfl_sync(0xffffffff, bl, 0);
        if (best == 0) break;                       // all lists exhausted
        if (lane == bl) {
            unsigned long long key = g_sel[c * SEL_CAP + ptr];
            unsigned idx = 0xFFFFFFFFu - (unsigned)(key & 0xFFFFFFFFull);
            out[k * 4 + 0] = g_boxes[idx * 4 + 0];
            out[k * 4 + 1] = g_boxes[idx * 4 + 1];
            out[k * 4 + 2] = g_boxes[idx * 4 + 2];
            out[k * 4 + 3] = g_boxes[idx * 4 + 3];
            out[800 + k]  = __uint_as_float(best);
            out[1000 + k] = (float)(c + 1);
            ptr++;
        }
        __syncwarp();
    }
}

// ---------------- launch ------------------------------------------------------
extern "C" void kernel_launch(void* const* d_in, const int* in_sizes, int n_in,
                              void* d_out, int out_size) {
    const float* logits = (const float*)d_in[0];   // [A,21]
    const float* reg    = (const float*)d_in[1];   // [A,4]
    const float* anc    = (const float*)d_in[2];   // [A,4]
    float* out = (float*)d_out;

    k_init<<<(NCLS * NB1 + 1023) / 1024, 1024>>>();
    k_prep<<<(AN + 255) / 256, 256>>>(logits, reg, anc);
    k_cut<<<1, 32>>>();
    dim3 gc((AN + 255) / 256, NCLS);
    k_collect<<<gc, 256>>>();
    k_final<<<NCLS, 512>>>();
    k_nms<<<NCLS, 512>>>();
    k_out<<<1, 32>>>(out, out_size);
}

// round 2
// speedup vs baseline: 1.3705x; 1.3705x over previous
#include <cuda_runtime.h>
#include <cstdint>

#define AN 200000
#define NCLS 20          // foreground classes (labels 1..20)
#define NB1 1024         // level-1 histogram bins
#define TOPK 400
#define SIDE_CAP 4096
#define SEL_CAP 512
#define DET 200
#define NW 13            // ceil(TOPK/32)
#define SCORE_T 0.01f
#define NMS_T 0.45f
#define BIN_BASE 0x3C23  // float bits of 0.01f >> 16

// ---------------- scratch (static device globals; no allocation) -------------
__device__ float              g_scores[NCLS * AN];      // masked fg scores [cls][anchor]
__device__ float              g_boxes[AN * 4];          // decoded+clipped boxes
__device__ int                g_hist1[NCLS * NB1];
__device__ int                g_cutbin[NCLS];           // -1 => select-all mode
__device__ int                g_need[NCLS];
__device__ unsigned long long g_sel[NCLS * SEL_CAP];    // (scorebits<<32)|(~idx)
__device__ int                g_selCnt[NCLS];
__device__ unsigned long long g_side[NCLS * SIDE_CAP];
__device__ int                g_sideCnt[NCLS];
__device__ int                g_nmsN[NCLS];
__device__ unsigned long long g_kept[NCLS * DET];       // compacted post-NMS keys
__device__ int                g_keptCnt[NCLS];

__device__ __forceinline__ int bin1_of(float s) {
    int b = (int)(__float_as_uint(s) >> 16) - BIN_BASE;
    return min(max(b, 0), NB1 - 1);
}

// ---------------- K0: zero counters/histograms -------------------------------
__global__ void k_init() {
    int t = blockIdx.x * blockDim.x + threadIdx.x;
    if (t < NCLS * NB1) g_hist1[t] = 0;
    if (t < NCLS) { g_selCnt[t] = 0; g_sideCnt[t] = 0; }
}

// ---------------- K1: softmax + decode + hist --------------------------------
__global__ void k_prep(const float* __restrict__ logits,
                       const float* __restrict__ reg,
                       const float* __restrict__ anc) {
    int i = blockIdx.x * blockDim.x + threadIdx.x;
    if (i >= AN) return;

    const float* L = logits + (long)i * 21;
    float e[21];
    float m = L[0];
#pragma unroll
    for (int c = 1; c < 21; c++) m = fmaxf(m, L[c]);
    float s = 0.f;
#pragma unroll
    for (int c = 0; c < 21; c++) { e[c] = expf(L[c] - m); s += e[c]; }

#pragma unroll
    for (int c = 1; c < 21; c++) {
        float sc = e[c] / s;
        float v = (sc > SCORE_T) ? sc : -1.0f;
        g_scores[(c - 1) * AN + i] = v;
        if (sc > SCORE_T) atomicAdd(&g_hist1[(c - 1) * NB1 + bin1_of(sc)], 1);
    }

    float ax1 = anc[i * 4 + 0], ay1 = anc[i * 4 + 1];
    float ax2 = anc[i * 4 + 2], ay2 = anc[i * 4 + 3];
    float aw = ax2 - ax1, ah = ay2 - ay1;
    float acx = ax1 + 0.5f * aw, acy = ay1 + 0.5f * ah;
    float dx = reg[i * 4 + 0] / 10.0f;
    float dy = reg[i * 4 + 1] / 10.0f;
    float dw = fminf(reg[i * 4 + 2] / 5.0f, 4.135166556742356f);
    float dh = fminf(reg[i * 4 + 3] / 5.0f, 4.135166556742356f);
    float pcx = dx * aw + acx, pcy = dy * ah + acy;
    float pw = expf(dw) * aw, ph = expf(dh) * ah;
    float bx1 = pcx - 0.5f * pw, by1 = pcy - 0.5f * ph;
    float bx2 = pcx + 0.5f * pw, by2 = pcy + 0.5f * ph;
    g_boxes[i * 4 + 0] = fminf(fmaxf(bx1, 0.f), 320.f);
    g_boxes[i * 4 + 1] = fminf(fmaxf(by1, 0.f), 320.f);
    g_boxes[i * 4 + 2] = fminf(fmaxf(bx2, 0.f), 320.f);
    g_boxes[i * 4 + 3] = fminf(fmaxf(by2, 0.f), 320.f);
}

// ---------------- K2: per-class rank-400 cutoff bin --------------------------
__global__ void k_cut() {
    int c = threadIdx.x;
    if (c >= NCLS) return;
    const int* h = &g_hist1[c * NB1];
    int total = 0;
    for (int b = 0; b < NB1; b++) total += h[b];
    if (total <= TOPK) { g_cutbin[c] = -1; g_need[c] = 0; return; }
    int cum = 0;
    for (int b = NB1 - 1; b >= 0; b--) {
        int hb = h[b];
        if (cum + hb >= TOPK) { g_cutbin[c] = b; g_need[c] = TOPK - cum; return; }
        cum += hb;
    }
}

// ---------------- K3: collect definite + cutoff-bin items (float4) -----------
__global__ void k_collect() {
    int c = blockIdx.y;
    int q = blockIdx.x * blockDim.x + threadIdx.x;   // quad index
    if (q * 4 >= AN) return;
    float4 v4 = *reinterpret_cast<const float4*>(&g_scores[c * AN + q * 4]);
    int cut = g_cutbin[c];
    float vs[4] = {v4.x, v4.y, v4.z, v4.w};
#pragma unroll
    for (int u = 0; u < 4; u++) {
        float v = vs[u];
        if (v <= SCORE_T) continue;
        unsigned i = (unsigned)(q * 4 + u);
        unsigned long long key =
            ((unsigned long long)__float_as_uint(v) << 32) | (0xFFFFFFFFu - i);
        if (cut < 0) {
            int p = atomicAdd(&g_selCnt[c], 1);
            g_sel[c * SEL_CAP + p] = key;
            continue;
        }
        int b = bin1_of(v);
        if (b > cut) {
            int p = atomicAdd(&g_selCnt[c], 1);
            g_sel[c * SEL_CAP + p] = key;
        } else if (b == cut) {
            int p = atomicAdd(&g_sideCnt[c], 1);
            if (p < SIDE_CAP) g_side[c * SIDE_CAP + p] = key;
        }
    }
}

// ---------------- bitonic sort (descending) in shared ------------------------
__device__ void bitonic_desc(unsigned long long* buf, int np2) {
    int tid = threadIdx.x, bd = blockDim.x;
    for (int k = 2; k <= np2; k <<= 1) {
        for (int j = k >> 1; j > 0; j >>= 1) {
            for (int t = tid; t < np2; t += bd) {
                int ixj = t ^ j;
                if (ixj > t) {
                    unsigned long long a = buf[t], b = buf[ixj];
                    bool desc = ((t & k) == 0);
                    if ((a < b) == desc) { buf[t] = b; buf[ixj] = a; }
                }
            }
            __syncthreads();
        }
    }
}

// ---------------- K4: finalize per-class top-400, sort ------------------------
__global__ void k_final() {
    __shared__ unsigned long long buf[SIDE_CAP];
    int c = blockIdx.x, tid = threadIdx.x;
    int cut = g_cutbin[c];
    int total;
    if (cut >= 0) {
        int n = min(g_sideCnt[c], SIDE_CAP);
        int np2 = 2; while (np2 < n) np2 <<= 1;
        for (int t = tid; t < np2; t += blockDim.x)
            buf[t] = (t < n) ? g_side[c * SIDE_CAP + t] : 0ull;
        __syncthreads();
        bitonic_desc(buf, np2);
        int need = g_need[c]; if (need > n) need = n;
        int base = g_selCnt[c];
        for (int t = tid; t < need; t += blockDim.x) g_sel[c * SEL_CAP + base + t] = buf[t];
        total = base + need;
        __syncthreads();
    } else {
        total = g_selCnt[c];
    }
    for (int t = tid; t < SEL_CAP; t += blockDim.x)
        buf[t] = (t < total) ? g_sel[c * SEL_CAP + t] : 0ull;
    __syncthreads();
    bitonic_desc(buf, SEL_CAP);
    for (int t = tid; t < SEL_CAP; t += blockDim.x) g_sel[c * SEL_CAP + t] = buf[t];
    if (tid == 0) g_nmsN[c] = total;
}

// ---------------- K5: per-class bitmask NMS + compaction ----------------------
__global__ void k_nms() {
    __shared__ float X1[TOPK], Y1[TOPK], X2[TOPK], Y2[TOPK], AR[TOPK];
    __shared__ unsigned long long keys[TOPK];
    __shared__ unsigned mask[TOPK * NW];     // bit j of word w: iou(i, w*32+b) > T, j>i
    __shared__ unsigned supw[NW];
    int c = blockIdx.x, tid = threadIdx.x, lane = tid & 31;
    int n = g_nmsN[c];

    for (int t = tid; t < n; t += blockDim.x) {
        unsigned long long key = g_sel[c * SEL_CAP + t];
        unsigned idx = 0xFFFFFFFFu - (unsigned)(key & 0xFFFFFFFFull);
        float x1 = g_boxes[idx * 4 + 0], y1 = g_boxes[idx * 4 + 1];
        float x2 = g_boxes[idx * 4 + 2], y2 = g_boxes[idx * 4 + 3];
        X1[t] = x1; Y1[t] = y1; X2[t] = x2; Y2[t] = y2;
        AR[t] = (x2 - x1) * (y2 - y1);
        keys[t] = key;
    }
    __syncthreads();

    int nw_used = (n + 31) >> 5;
    // parallel IoU bitmask build
    for (int task = tid; task < n * nw_used; task += blockDim.x) {
        int i = task / nw_used, w = task % nw_used;
        unsigned m = 0;
        int jbase = w * 32;
        if (jbase + 31 > i) {
            float xi1 = X1[i], yi1 = Y1[i], xi2 = X2[i], yi2 = Y2[i], ai = AR[i];
#pragma unroll 4
            for (int b = 0; b < 32; b++) {
                int j = jbase + b;
                if (j > i && j < n) {
                    float lx = fmaxf(xi1, X1[j]), ly = fmaxf(yi1, Y1[j]);
                    float rx = fminf(xi2, X2[j]), ry = fminf(yi2, Y2[j]);
                    float w_ = fmaxf(rx - lx, 0.f), h_ = fmaxf(ry - ly, 0.f);
                    float inter = w_ * h_;
                    float iou = inter / (ai + AR[j] - inter);   // NaN>T==false
                    if (iou > NMS_T) m |= (1u << b);
                }
            }
        }
        mask[i * NW + w] = m;
    }
    __syncthreads();

    // register-resident serial sweep (warp 0); lane w owns suppression word w
    if (tid < 32) {
        unsigned sup = 0;
        for (int i = 0; i < n; i++) {
            unsigned wi = __shfl_sync(0xffffffff, sup, i >> 5);
            if (!((wi >> (i & 31)) & 1)) {
                if (lane < nw_used) sup |= mask[i * NW + lane];
            }
        }
        if (lane < NW) supw[lane] = sup;
    }
    __syncthreads();

    // compact kept keys (score-desc order preserved), cap DET
    if (tid < 32) {
        int outc = 0;
        for (int base = 0; base < n; base += 32) {
            int i = base + lane;
            bool kept = (i < n) && !((supw[i >> 5] >> (i & 31)) & 1);
            unsigned bal = __ballot_sync(0xffffffff, kept);
            int pos = outc + __popc(bal & ((1u << lane) - 1));
            if (kept && pos < DET) g_kept[c * DET + pos] = keys[i];
            outc += __popc(bal);
        }
        if (lane == 0) g_keptCnt[c] = min(outc, DET);
    }
}

// ---------------- K6: 20-way merge of kept lists, write top-200 --------------
__global__ void k_out(float* __restrict__ out, int out_size) {
    __shared__ unsigned long long kk[NCLS * DET];    // 32KB
    __shared__ int cnts[NCLS];
    __shared__ unsigned long long wkey[DET];
    __shared__ int wcls[DET];
    __shared__ int nwin;
    int tid = threadIdx.x;

    for (int t = tid; t < out_size; t += blockDim.x) out[t] = 0.f;
    if (tid < NCLS) cnts[tid] = g_keptCnt[tid];
    for (int t = tid; t < NCLS * DET; t += blockDim.x) kk[t] = g_kept[t];
    __syncthreads();

    if (tid < 32) {
        int lane = tid;
        int c = lane;
        int cnt = (c < NCLS) ? cnts[c] : 0;
        int p = 0;
        unsigned long long cur = (p < cnt) ? kk[c * DET + p] : 0ull;
        int k = 0;
        for (; k < DET; k++) {
            unsigned sb = (unsigned)(cur >> 32);
            unsigned best = __reduce_max_sync(0xffffffff, sb);
            if (best == 0) break;
            unsigned bal = __ballot_sync(0xffffffff, sb == best);
            int bl = __ffs(bal) - 1;                 // lowest lane = lowest class
            if (lane == bl) {
                wkey[k] = cur; wcls[k] = c;
                p++;
                cur = (p < cnt) ? kk[c * DET + p] : 0ull;
            }
            __syncwarp();
        }
        if (lane == 0) nwin = k;
    }
    __syncthreads();

    int nw_ = nwin;
    for (int k = tid; k < nw_; k += blockDim.x) {
        unsigned long long key = wkey[k];
        unsigned idx = 0xFFFFFFFFu - (unsigned)(key & 0xFFFFFFFFull);
        out[k * 4 + 0] = g_boxes[idx * 4 + 0];
        out[k * 4 + 1] = g_boxes[idx * 4 + 1];
        out[k * 4 + 2] = g_boxes[idx * 4 + 2];
        out[k * 4 + 3] = g_boxes[idx * 4 + 3];
        out[800 + k]  = __uint_as_float((unsigned)(key >> 32));
        out[1000 + k] = (float)(wcls[k] + 1);
    }
}

// ---------------- launch ------------------------------------------------------
extern "C" void kernel_launch(void* const* d_in, const int* in_sizes, int n_in,
                              void* d_out, int out_size) {
    const float* logits = (const float*)d_in[0];   // [A,21]
    const float* reg    = (const float*)d_in[1];   // [A,4]
    const float* anc    = (const float*)d_in[2];   // [A,4]
    float* out = (float*)d_out;

    k_init<<<(NCLS * NB1 + 1023) / 1024, 1024>>>();
    k_prep<<<(AN + 255) / 256, 256>>>(logits, reg, anc);
    k_cut<<<1, 32>>>();
    dim3 gc((AN / 4 + 255) / 256, NCLS);
    k_collect<<<gc, 256>>>();
    k_final<<<NCLS, 512>>>();
    k_nms<<<NCLS, 512>>>();
    k_out<<<1, 256>>>(out, out_size);
}

// round 4
// speedup vs baseline: 1.5137x; 1.1045x over previous
#include <cuda_runtime.h>
#include <cstdint>

#define AN 200000
#define NCLS 20          // foreground classes (labels 1..20)
#define NB1 1024         // histogram bins (top-16-bit float)
#define TOPK 400
#define SEL_CAP 2048
#define DET 200
#define NW 13            // ceil(TOPK/32)
#define SCORE_T 0.01f
#define NMS_T 0.45f
#define BIN_BASE 0x3C23  // float bits of 0.01f >> 16

// ---------------- scratch (static device globals; no allocation) -------------
__device__ float              g_scores[NCLS * AN];      // APPROX fg scores [cls][anchor]
__device__ float              g_boxes[AN * 4];          // decoded+clipped boxes
__device__ int                g_hist1[NCLS * NB1];
__device__ int                g_cut[NCLS];              // cutbin-2 (widened); -1 => take all
__device__ unsigned long long g_sel[NCLS * SEL_CAP];    // EXACT keys (scorebits<<32)|(~idx)
__device__ int                g_selCnt[NCLS];
__device__ int                g_nmsN[NCLS];
__device__ unsigned long long g_kept[NCLS * DET];       // compacted post-NMS keys
__device__ int                g_keptCnt[NCLS];

__device__ __forceinline__ int bin1_of(float s) {
    int b = (int)(__float_as_uint(s) >> 16) - BIN_BASE;
    return min(max(b, 0), NB1 - 1);
}

// EXACT softmax score for (anchor i, fg class cls): identical op order to the
// R2 kernel that passed at rel_err 1.27e-7 (sequential max, sequential sum, div.rn).
__device__ float exact_score(const float* __restrict__ logits, unsigned i, int cls) {
    const float* L = logits + (size_t)i * 21;
    float m = L[0];
#pragma unroll
    for (int c = 1; c < 21; c++) m = fmaxf(m, L[c]);
    float s = 0.f, ev = 0.f;
#pragma unroll
    for (int c = 0; c < 21; c++) {
        float e = expf(L[c] - m);
        s += e;
        if (c == cls + 1) ev = e;
    }
    return ev / s;
}

// ---------------- K0: zero counters/histograms -------------------------------
__global__ void k_init() {
    int t = blockIdx.x * blockDim.x + threadIdx.x;
    if (t < NCLS * NB1) g_hist1[t] = 0;
    if (t < NCLS) g_selCnt[t] = 0;
}

// ---------------- K1: APPROX softmax + decode + hist -------------------------
__global__ void k_prep(const float* __restrict__ logits,
                       const float* __restrict__ reg,
                       const float* __restrict__ anc) {
    __shared__ float sm[256 * 21];
    int blk = blockIdx.x, t = threadIdx.x;

    // stage this block's logits via float4 (fully coalesced)
    long base4 = (long)blk * (256 * 21 / 4);
    int cnt4 = (int)min((long)(256 * 21 / 4), (long)(AN * 21 / 4) - base4);
    const float4* Lv = (const float4*)logits;
    for (int u = t; u < cnt4; u += 256)
        ((float4*)sm)[u] = Lv[base4 + u];
    __syncthreads();

    int i = blk * 256 + t;
    if (i >= AN) return;
    const float* L = sm + t * 21;

    float m = L[0];
#pragma unroll
    for (int c = 1; c < 21; c++) m = fmaxf(m, L[c]);
    float e[21];
    float s = 0.f;
#pragma unroll
    for (int c = 0; c < 21; c++) { e[c] = __expf(L[c] - m); s += e[c]; }
    float r = __fdividef(1.0f, s);

#pragma unroll
    for (int c = 1; c < 21; c++) {
        float sc = e[c] * r;                       // approx score (~1e-6 rel err)
        g_scores[(c - 1) * AN + i] = sc;
        if (sc > 0.0099f) atomicAdd(&g_hist1[(c - 1) * NB1 + bin1_of(sc)], 1);
    }

    // decode (exact math, matches reference) + clip to 320x320
    float4 a4 = *(const float4*)(anc + (size_t)i * 4);
    float4 r4 = *(const float4*)(reg + (size_t)i * 4);
    float aw = a4.z - a4.x, ah = a4.w - a4.y;
    float acx = a4.x + 0.5f * aw, acy = a4.y + 0.5f * ah;
    float dx = r4.x / 10.0f;
    float dy = r4.y / 10.0f;
    float dw = fminf(r4.z / 5.0f, 4.135166556742356f);
    float dh = fminf(r4.w / 5.0f, 4.135166556742356f);
    float pcx = dx * aw + acx, pcy = dy * ah + acy;
    float pw = expf(dw) * aw, ph = expf(dh) * ah;
    float4 b4;
    b4.x = fminf(fmaxf(pcx - 0.5f * pw, 0.f), 320.f);
    b4.y = fminf(fmaxf(pcy - 0.5f * ph, 0.f), 320.f);
    b4.z = fminf(fmaxf(pcx + 0.5f * pw, 0.f), 320.f);
    b4.w = fminf(fmaxf(pcy + 0.5f * ph, 0.f), 320.f);
    *(float4*)(g_boxes + (size_t)i * 4) = b4;
}

// ---------------- K2: per-class widened rank-400 cutoff bin ------------------
__global__ void k_cut() {
    int c = threadIdx.x;
    if (c >= NCLS) return;
    const int* h = &g_hist1[c * NB1];
    int cum = 0;
    int cut = -1;                         // -1 => take everything above band
    for (int b = NB1 - 1; b >= 0; b--) {
        cum += h[b];
        if (cum >= TOPK) { cut = b - 2; break; }   // widen by 2 bins (approx safety)
    }
    if (cut < 4) cut = -1;                // near-threshold: just take everything
    g_cut[c] = cut;
}

// ---------------- K3: collect candidates, EXACT recompute on push ------------
__global__ void k_collect(const float* __restrict__ logits) {
    int c = blockIdx.y;
    int q = blockIdx.x * blockDim.x + threadIdx.x;   // quad index
    if (q * 4 >= AN) return;
    float4 v4 = *reinterpret_cast<const float4*>(&g_scores[c * AN + q * 4]);
    int cut = g_cut[c];
    float vs[4] = {v4.x, v4.y, v4.z, v4.w};
#pragma unroll
    for (int u = 0; u < 4; u++) {
        float v = vs[u];
        if (v <= 0.0099f) continue;
        if (cut >= 0 && bin1_of(v) < cut) continue;
        unsigned i = (unsigned)(q * 4 + u);
        float ex = exact_score(logits, i, c);        // matches reference path
        if (ex <= SCORE_T) continue;
        unsigned long long key =
            ((unsigned long long)__float_as_uint(ex) << 32) | (0xFFFFFFFFu - i);
        int p = atomicAdd(&g_selCnt[c], 1);
        if (p < SEL_CAP) g_sel[c * SEL_CAP + p] = key;
    }
}

// ---------------- bitonic sort (descending) in shared ------------------------
__device__ void bitonic_desc(unsigned long long* buf, int np2) {
    int tid = threadIdx.x, bd = blockDim.x;
    for (int k = 2; k <= np2; k <<= 1) {
        for (int j = k >> 1; j > 0; j >>= 1) {
            for (int t = tid; t < np2; t += bd) {
                int ixj = t ^ j;
                if (ixj > t) {
                    unsigned long long a = buf[t], b = buf[ixj];
                    bool desc = ((t & k) == 0);
                    if ((a < b) == desc) { buf[t] = b; buf[ixj] = a; }
                }
            }
            __syncthreads();
        }
    }
}

// ---------------- K4: sort superset, truncate to exact top-400 ----------------
__global__ void k_final() {
    __shared__ unsigned long long buf[SEL_CAP];
    int c = blockIdx.x, tid = threadIdx.x;
    int n = min(g_selCnt[c], SEL_CAP);
    int np2 = 2; while (np2 < n) np2 <<= 1;
    for (int t = tid; t < np2; t += blockDim.x)
        buf[t] = (t < n) ? g_sel[c * SEL_CAP + t] : 0ull;
    __syncthreads();
    bitonic_desc(buf, np2);
    int keep = min(n, TOPK);
    for (int t = tid; t < keep; t += blockDim.x) g_sel[c * SEL_CAP + t] = buf[t];
    if (tid == 0) g_nmsN[c] = keep;
}

// ---------------- K5: per-class bitmask NMS + compaction ----------------------
__global__ void k_nms() {
    __shared__ float X1[TOPK], Y1[TOPK], X2[TOPK], Y2[TOPK], AR[TOPK];
    __shared__ unsigned long long keys[TOPK];
    __shared__ unsigned mask[TOPK * NW];
    __shared__ unsigned supw[NW];
    int c = blockIdx.x, tid = threadIdx.x, lane = tid & 31;
    int n = g_nmsN[c];

    for (int t = tid; t < n; t += blockDim.x) {
        unsigned long long key = g_sel[c * SEL_CAP + t];
        unsigned idx = 0xFFFFFFFFu - (unsigned)(key & 0xFFFFFFFFull);
        float x1 = g_boxes[idx * 4 + 0], y1 = g_boxes[idx * 4 + 1];
        float x2 = g_boxes[idx * 4 + 2], y2 = g_boxes[idx * 4 + 3];
        X1[t] = x1; Y1[t] = y1; X2[t] = x2; Y2[t] = y2;
        AR[t] = (x2 - x1) * (y2 - y1);
        keys[t] = key;
    }
    __syncthreads();

    int nw_used = (n + 31) >> 5;
    for (int task = tid; task < n * nw_used; task += blockDim.x) {
        int i = task / nw_used, w = task % nw_used;
        unsigned m = 0;
        int jbase = w * 32;
        if (jbase + 31 > i) {
            float xi1 = X1[i], yi1 = Y1[i], xi2 = X2[i], yi2 = Y2[i], ai = AR[i];
#pragma unroll 4
            for (int b = 0; b < 32; b++) {
                int j = jbase + b;
                if (j > i && j < n) {
                    float lx = fmaxf(xi1, X1[j]), ly = fmaxf(yi1, Y1[j]);
                    float rx = fminf(xi2, X2[j]), ry = fminf(yi2, Y2[j]);
                    float w_ = fmaxf(rx - lx, 0.f), h_ = fmaxf(ry - ly, 0.f);
                    float inter = w_ * h_;
                    float iou = inter / (ai + AR[j] - inter);   // NaN>T==false
                    if (iou > NMS_T) m |= (1u << b);
                }
            }
        }
        mask[i * NW + w] = m;
    }
    __syncthreads();

    if (tid < 32) {
        unsigned sup = 0;
        for (int i = 0; i < n; i++) {
            unsigned wi = __shfl_sync(0xffffffff, sup, i >> 5);
            if (!((wi >> (i & 31)) & 1)) {
                if (lane < nw_used) sup |= mask[i * NW + lane];
            }
        }
        if (lane < NW) supw[lane] = sup;
    }
    __syncthreads();

    if (tid < 32) {
        int outc = 0;
        for (int base = 0; base < n; base += 32) {
            int i = base + lane;
            bool kept = (i < n) && !((supw[i >> 5] >> (i & 31)) & 1);
            unsigned bal = __ballot_sync(0xffffffff, kept);
            int pos = outc + __popc(bal & ((1u << lane) - 1));
            if (kept && pos < DET) g_kept[c * DET + pos] = keys[i];
            outc += __popc(bal);
        }
        if (lane == 0) g_keptCnt[c] = min(outc, DET);
    }
}

// ---------------- K6: 20-way merge of kept lists, write top-200 --------------
__global__ void k_out(float* __restrict__ out, int out_size) {
    __shared__ unsigned long long kk[NCLS * DET];
    __shared__ int cnts[NCLS];
    __shared__ unsigned long long wkey[DET];
    __shared__ int wcls[DET];
    __shared__ int nwin;
    int tid = threadIdx.x;

    for (int t = tid; t < out_size; t += blockDim.x) out[t] = 0.f;
    if (tid < NCLS) cnts[tid] = g_keptCnt[tid];
    for (int t = tid; t < NCLS * DET; t += blockDim.x) kk[t] = g_kept[t];
    __syncthreads();

    if (tid < 32) {
        int lane = tid;
        int c = lane;
        int cnt = (c < NCLS) ? cnts[c] : 0;
        int p = 0;
        unsigned long long cur = (p < cnt) ? kk[c * DET + p] : 0ull;
        int k = 0;
        for (; k < DET; k++) {
            unsigned sb = (unsigned)(cur >> 32);
            unsigned best = __reduce_max_sync(0xffffffff, sb);
            if (best == 0) break;
            unsigned bal = __ballot_sync(0xffffffff, sb == best);
            int bl = __ffs(bal) - 1;                 // lowest lane = lowest class
            if (lane == bl) {
                wkey[k] = cur; wcls[k] = c;
                p++;
                cur = (p < cnt) ? kk[c * DET + p] : 0ull;
            }
            __syncwarp();
        }
        if (lane == 0) nwin = k;
    }
    __syncthreads();

    int nw_ = nwin;
    for (int k = tid; k < nw_; k += blockDim.x) {
        unsigned long long key = wkey[k];
        unsigned idx = 0xFFFFFFFFu - (unsigned)(key & 0xFFFFFFFFull);
        out[k * 4 + 0] = g_boxes[idx * 4 + 0];
        out[k * 4 + 1] = g_boxes[idx * 4 + 1];
        out[k * 4 + 2] = g_boxes[idx * 4 + 2];
        out[k * 4 + 3] = g_boxes[idx * 4 + 3];   // <-- the R3 bug: this line was missing
        out[800 + k]  = __uint_as_float((unsigned)(key >> 32));
        out[1000 + k] = (float)(wcls[k] + 1);
    }
}

// ---------------- launch ------------------------------------------------------
extern "C" void kernel_launch(void* const* d_in, const int* in_sizes, int n_in,
                              void* d_out, int out_size) {
    const float* logits = (const float*)d_in[0];   // [A,21]
    const float* reg    = (const float*)d_in[1];   // [A,4]
    const float* anc    = (const float*)d_in[2];   // [A,4]
    float* out = (float*)d_out;

    k_init<<<(NCLS * NB1 + 1023) / 1024, 1024>>>();
    k_prep<<<(AN + 255) / 256, 256>>>(logits, reg, anc);
    k_cut<<<1, 32>>>();
    dim3 gc((AN / 4 + 255) / 256, NCLS);
    k_collect<<<gc, 256>>>(logits);
    k_final<<<NCLS, 512>>>();
    k_nms<<<NCLS, 512>>>();
    k_out<<<1, 256>>>(out, out_size);
}

// round 5
// speedup vs baseline: 1.5948x; 1.0535x over previous
#include <cuda_runtime.h>
#include <cstdint>

#define AN 200000
#define NCLS 20          // foreground classes (labels 1..20)
#define NBIN 256         // log-domain histogram bins
#define TOPK 400
#define SEL_CAP 2048
#define DET 200
#define NW 13            // ceil(TOPK/32)
#define NMS_T 0.45f
#define K2E 1.44269504088896f

// bin = clamp((int)fmaf(y, 38.2, 255.4)) where y = log2(score); score=1 -> 255,
// score~0.0099 -> 1, below -> 0. ~1.8% relative bin width.

// ---------------- scratch (static device globals; no allocation) -------------
__device__ unsigned           g_binsP[AN * 8];          // 20 bin bytes/anchor, 32B padded
__device__ int                g_hist[NCLS * NBIN];
__device__ int                g_cut[NCLS];              // widened cutoff bin (>=1)
__device__ unsigned long long g_sel[NCLS * SEL_CAP];    // EXACT keys (scorebits<<32)|(~idx)
__device__ int                g_selCnt[NCLS];
__device__ unsigned long long g_kept[NCLS * DET];       // compacted post-NMS keys
__device__ float4             g_keptBox[NCLS * DET];    // decoded boxes of kept dets
__device__ int                g_keptCnt[NCLS];

// ---------------- K0: zero counters/histogram --------------------------------
__global__ void k_init() {
    int t = blockIdx.x * blockDim.x + threadIdx.x;
    if (t < NCLS * NBIN) g_hist[t] = 0;
    if (t < NCLS) g_selCnt[t] = 0;
}

// ---------------- K1: log-domain bins + histogram (4 anchors/thread) ---------
__global__ void __launch_bounds__(256) k_prep(const float* __restrict__ logits) {
    int q = blockIdx.x * blockDim.x + threadIdx.x;   // quad of anchors
    if (q * 4 >= AN) return;
    union { float4 v[21]; float f[84]; } u;
    const float4* src = (const float4*)logits + (size_t)q * 21;   // 84 floats, 16B aligned
#pragma unroll
    for (int k = 0; k < 21; k++) u.v[k] = src[k];

#pragma unroll
    for (int a = 0; a < 4; a++) {
        float S = 0.f;
#pragma unroll
        for (int c = 0; c < 21; c++) S += exp2f(u.f[a * 21 + c] * K2E);
        float lgS = __log2f(S);
        unsigned w[5] = {0, 0, 0, 0, 0};
#pragma unroll
        for (int c = 1; c < 21; c++) {
            float y = fmaf(u.f[a * 21 + c], K2E, -lgS);     // ~log2(score)
            int bin = (int)fmaf(y, 38.2f, 255.4f);
            bin = max(0, min(255, bin));
            if (bin > 0) atomicAdd(&g_hist[(c - 1) * NBIN + bin], 1);
            int cc = c - 1;
            w[cc >> 2] |= (unsigned)bin << ((cc & 3) * 8);
        }
        unsigned i = (unsigned)(q * 4 + a);
        *(uint4*)&g_binsP[(size_t)i * 8] = make_uint4(w[0], w[1], w[2], w[3]);
        g_binsP[(size_t)i * 8 + 4] = w[4];
    }
}

// ---------------- K2: per-class widened rank-400 cutoff ----------------------
__global__ void k_cut() {
    int wid = threadIdx.x >> 5, lane = threadIdx.x & 31;
    for (int c = wid; c < NCLS; c += 8) {
        int cum = 0, cutbin = 1;
        bool found = false;
        for (int base = NBIN - 32; base >= 0; base -= 32) {
            int b = base + 31 - lane;                 // lane 0 = highest bin
            int v = g_hist[c * NBIN + b];
            int s = v;                                 // inclusive scan (count from top)
#pragma unroll
            for (int off = 1; off < 32; off <<= 1) {
                int t = __shfl_up_sync(0xffffffffu, s, off);
                if (lane >= off) s += t;
            }
            unsigned bal = __ballot_sync(0xffffffffu, (cum + s) >= TOPK);
            int tot = __shfl_sync(0xffffffffu, s, 31);
            if (bal) {
                int l = __ffs(bal) - 1;
                cutbin = base + 31 - l;
                found = true;
                break;
            }
            cum += tot;
        }
        if (lane == 0) g_cut[c] = found ? max(cutbin - 2, 1) : 1;
    }
}

// ---------------- K3: collect candidates, EXACT recompute on push ------------
__global__ void k_collect(const float* __restrict__ logits) {
    __shared__ int scut[NCLS];
    if (threadIdx.x < NCLS) scut[threadIdx.x] = g_cut[threadIdx.x];
    __syncthreads();
    int i = blockIdx.x * blockDim.x + threadIdx.x;
    if (i >= AN) return;
    uint4 w4 = *(const uint4*)&g_binsP[(size_t)i * 8];
    unsigned w5 = g_binsP[(size_t)i * 8 + 4];
    unsigned wv[5] = {w4.x, w4.y, w4.z, w4.w, w5};
    bool any = false;
#pragma unroll
    for (int c = 0; c < NCLS; c++) {
        int b = (wv[c >> 2] >> ((c & 3) * 8)) & 255;
        if (b >= scut[c]) any = true;
    }
    if (!any) return;

    // exact softmax pieces (accurate expf, div.rn) — matches reference path
    const float* L = logits + (size_t)i * 21;
    float Lr[21];
#pragma unroll
    for (int c = 0; c < 21; c++) Lr[c] = L[c];
    float m = Lr[0];
#pragma unroll
    for (int c = 1; c < 21; c++) m = fmaxf(m, Lr[c]);
    float S = 0.f;
#pragma unroll
    for (int c = 0; c < 21; c++) S += expf(Lr[c] - m);

#pragma unroll
    for (int c = 0; c < NCLS; c++) {
        int b = (wv[c >> 2] >> ((c & 3) * 8)) & 255;
        if (b < scut[c]) continue;
        float ex = expf(Lr[c + 1] - m) / S;
        if (ex <= 0.01f) continue;
        unsigned long long key =
            ((unsigned long long)__float_as_uint(ex) << 32) | (0xFFFFFFFFu - (unsigned)i);
        int p = atomicAdd(&g_selCnt[c], 1);
        if (p < SEL_CAP) g_sel[c * SEL_CAP + p] = key;
    }
}

// ---------------- bitonic sort (descending) in shared ------------------------
__device__ void bitonic_desc(unsigned long long* buf, int np2) {
    int tid = threadIdx.x, bd = blockDim.x;
    for (int k = 2; k <= np2; k <<= 1) {
        for (int j = k >> 1; j > 0; j >>= 1) {
            for (int t = tid; t < np2; t += bd) {
                int ixj = t ^ j;
                if (ixj > t) {
                    unsigned long long a = buf[t], b = buf[ixj];
                    bool desc = ((t & k) == 0);
                    if ((a < b) == desc) { buf[t] = b; buf[ixj] = a; }
                }
            }
            __syncthreads();
        }
    }
}

// ---------------- K4: sort + decode top-400 + bitmask NMS + compact ----------
__global__ void k_sortnms(const float* __restrict__ reg,
                          const float* __restrict__ anc) {
    __shared__ unsigned long long buf[SEL_CAP];        // 16 KB
    __shared__ float X1[TOPK], Y1[TOPK], X2[TOPK], Y2[TOPK], AR[TOPK];
    __shared__ unsigned mask[TOPK * NW];
    __shared__ unsigned supw[NW];
    int c = blockIdx.x, tid = threadIdx.x, lane = tid & 31;
    int n = min(g_selCnt[c], SEL_CAP);
    int np2 = 2; while (np2 < n) np2 <<= 1;
    for (int t = tid; t < np2; t += blockDim.x)
        buf[t] = (t < n) ? g_sel[c * SEL_CAP + t] : 0ull;
    __syncthreads();
    bitonic_desc(buf, np2);
    int nn = min(n, TOPK);

    // decode boxes for the top-nn only (accurate expf, reference formula + clip)
    for (int t = tid; t < nn; t += blockDim.x) {
        unsigned idx = 0xFFFFFFFFu - (unsigned)(buf[t] & 0xFFFFFFFFull);
        float4 a4 = *(const float4*)(anc + (size_t)idx * 4);
        float4 r4 = *(const float4*)(reg + (size_t)idx * 4);
        float aw = a4.z - a4.x, ah = a4.w - a4.y;
        float acx = a4.x + 0.5f * aw, acy = a4.y + 0.5f * ah;
        float dx = r4.x / 10.0f, dy = r4.y / 10.0f;
        float dw = fminf(r4.z / 5.0f, 4.135166556742356f);
        float dh = fminf(r4.w / 5.0f, 4.135166556742356f);
        float pcx = dx * aw + acx, pcy = dy * ah + acy;
        float pw = expf(dw) * aw, ph = expf(dh) * ah;
        float x1 = fminf(fmaxf(pcx - 0.5f * pw, 0.f), 320.f);
        float y1 = fminf(fmaxf(pcy - 0.5f * ph, 0.f), 320.f);
        float x2 = fminf(fmaxf(pcx + 0.5f * pw, 0.f), 320.f);
        float y2 = fminf(fmaxf(pcy + 0.5f * ph, 0.f), 320.f);
        X1[t] = x1; Y1[t] = y1; X2[t] = x2; Y2[t] = y2;
        AR[t] = (x2 - x1) * (y2 - y1);
    }
    __syncthreads();

    int nw_used = (nn + 31) >> 5;
    for (int task = tid; task < nn * nw_used; task += blockDim.x) {
        int i = task / nw_used, w = task % nw_used;
        unsigned m = 0;
        int jbase = w * 32;
        if (jbase + 31 > i) {
            float xi1 = X1[i], yi1 = Y1[i], xi2 = X2[i], yi2 = Y2[i], ai = AR[i];
#pragma unroll 4
            for (int b = 0; b < 32; b++) {
                int j = jbase + b;
                if (j > i && j < nn) {
                    float lx = fmaxf(xi1, X1[j]), ly = fmaxf(yi1, Y1[j]);
                    float rx = fminf(xi2, X2[j]), ry = fminf(yi2, Y2[j]);
                    float w_ = fmaxf(rx - lx, 0.f), h_ = fmaxf(ry - ly, 0.f);
                    float inter = w_ * h_;
                    float iou = inter / (ai + AR[j] - inter);   // NaN>T==false
                    if (iou > NMS_T) m |= (1u << b);
                }
            }
        }
        mask[i * NW + w] = m;
    }
    __syncthreads();

    if (tid < 32) {
        unsigned sup = 0;
        for (int i = 0; i < nn; i++) {
            unsigned wi = __shfl_sync(0xffffffff, sup, i >> 5);
            if (!((wi >> (i & 31)) & 1)) {
                if (lane < nw_used) sup |= mask[i * NW + lane];
            }
        }
        if (lane < NW) supw[lane] = sup;
    }
    __syncthreads();

    if (tid < 32) {
        int outc = 0;
        for (int base = 0; base < nn; base += 32) {
            int i = base + lane;
            bool kept = (i < nn) && !((supw[i >> 5] >> (i & 31)) & 1);
            unsigned bal = __ballot_sync(0xffffffff, kept);
            int pos = outc + __popc(bal & ((1u << lane) - 1));
            if (kept && pos < DET) {
                g_kept[c * DET + pos] = buf[i];
                g_keptBox[c * DET + pos] = make_float4(X1[i], Y1[i], X2[i], Y2[i]);
            }
            outc += __popc(bal);
        }
        if (lane == 0) g_keptCnt[c] = min(outc, DET);
    }
}

// ---------------- K5: 20-way merge of kept lists, write top-200 --------------
__global__ void k_out(float* __restrict__ out, int out_size) {
    __shared__ unsigned long long kk[NCLS * DET];
    __shared__ int cnts[NCLS];
    __shared__ unsigned long long wkey[DET];
    __shared__ int wcls[DET];
    __shared__ int wpos[DET];
    __shared__ int nwin;
    int tid = threadIdx.x;

    for (int t = tid; t < out_size; t += blockDim.x) out[t] = 0.f;
    if (tid < NCLS) cnts[tid] = g_keptCnt[tid];
    for (int t = tid; t < NCLS * DET; t += blockDim.x) kk[t] = g_kept[t];
    __syncthreads();

    if (tid < 32) {
        int lane = tid;
        int c = lane;
        int cnt = (c < NCLS) ? cnts[c] : 0;
        int p = 0;
        unsigned long long cur = (p < cnt) ? kk[c * DET + p] : 0ull;
        int k = 0;
        for (; k < DET; k++) {
            unsigned sb = (unsigned)(cur >> 32);
            unsigned best = __reduce_max_sync(0xffffffff, sb);
            if (best == 0) break;
            unsigned bal = __ballot_sync(0xffffffff, sb == best);
            int bl = __ffs(bal) - 1;                 // lowest lane = lowest class
            if (lane == bl) {
                wkey[k] = cur; wcls[k] = c; wpos[k] = p;
                p++;
                cur = (p < cnt) ? kk[c * DET + p] : 0ull;
            }
            __syncwarp();
        }
        if (lane == 0) nwin = k;
    }
    __syncthreads();

    int nw_ = nwin;
    for (int k = tid; k < nw_; k += blockDim.x) {
        int c = wcls[k];
        float4 bx = g_keptBox[c * DET + wpos[k]];
        *(float4*)(out + (size_t)k * 4) = bx;
        out[800 + k]  = __uint_as_float((unsigned)(wkey[k] >> 32));
        out[1000 + k] = (float)(c + 1);
    }
}

// ---------------- launch ------------------------------------------------------
extern "C" void kernel_launch(void* const* d_in, const int* in_sizes, int n_in,
                              void* d_out, int out_size) {
    const float* logits = (const float*)d_in[0];   // [A,21]
    const float* reg    = (const float*)d_in[1];   // [A,4]
    const float* anc    = (const float*)d_in[2];   // [A,4]
    float* out = (float*)d_out;

    k_init<<<(NCLS * NBIN + 1023) / 1024, 1024>>>();
    k_prep<<<(AN / 4 + 255) / 256, 256>>>(logits);
    k_cut<<<1, 256>>>();
    k_collect<<<(AN + 255) / 256, 256>>>(logits);
    k_sortnms<<<NCLS, 512>>>(reg, anc);
    k_out<<<1, 256>>>(out, out_size);
}

// round 7
// speedup vs baseline: 1.7789x; 1.1154x over previous
#include <cuda_runtime.h>
#include <cstdint>

#define AN 200000
#define NCLS 20          // foreground classes (labels 1..20)
#define NBIN 256         // log-domain histogram bins
#define TOPK 400
#define SEL_CAP 4096
#define DET 200
#define NW 13            // ceil(TOPK/32)
#define NMS_T 0.45f
#define K2E 1.44269504088896f

// ---------------- scratch (static device globals; no allocation) -------------
__device__ unsigned           g_binsP[AN * 8];          // 20 bin bytes/anchor, 32B stride
__device__ int                g_hist[NCLS * NBIN];
__device__ int                g_cut[NCLS];              // widened cutoff bin (>=1)
__device__ unsigned           g_cutPack[5];             // cut bytes packed like bins
__device__ unsigned           g_q[AN];                  // survivor anchor queue
__device__ int                g_qCnt;
__device__ unsigned long long g_sel[NCLS * SEL_CAP];    // EXACT keys (scorebits<<32)|(~idx)
__device__ int                g_selCnt[NCLS];
__device__ unsigned long long g_kept[NCLS * DET];       // compacted post-NMS keys
__device__ float4             g_keptBox[NCLS * DET];
__device__ int                g_keptCnt[NCLS];

// ---------------- K1: log-domain bins + block-private histogram --------------
// bin = clamp((int)fmaf(log2(score), 38.2, 255.4), 0, 255); score 0.0099 -> ~1.
__global__ void __launch_bounds__(256) k_prep(const float* __restrict__ logits) {
    __shared__ int h[NCLS * NBIN];                     // 20KB private histogram
    int tid = threadIdx.x;
    for (int t = tid; t < NCLS * NBIN; t += 256) h[t] = 0;
    __syncthreads();

    int q = blockIdx.x * 256 + tid;                    // quad of 4 anchors
    if (q < AN / 4) {
        const float4* src = (const float4*)logits + (size_t)q * 21;  // 84 floats
        // pass 1: per-anchor sum of exp (values consumed immediately, low regs)
        float S[4] = {0.f, 0.f, 0.f, 0.f};
#pragma unroll
        for (int k = 0; k < 21; k++) {
            float4 v = src[k];
            S[(4 * k + 0) / 21] += exp2f(v.x * K2E);
            S[(4 * k + 1) / 21] += exp2f(v.y * K2E);
            S[(4 * k + 2) / 21] += exp2f(v.z * K2E);
            S[(4 * k + 3) / 21] += exp2f(v.w * K2E);
        }
        float lg[4];
#pragma unroll
        for (int a = 0; a < 4; a++) lg[a] = __log2f(S[a]);

        // pass 2: reload (L1 hits), compute bins, hist + pack
        unsigned w[20];
#pragma unroll
        for (int t = 0; t < 20; t++) w[t] = 0;
#pragma unroll
        for (int k = 0; k < 21; k++) {
            float4 v = src[k];
            float e[4] = {v.x, v.y, v.z, v.w};
#pragma unroll
            for (int j = 0; j < 4; j++) {
                int f = 4 * k + j, a = f / 21, c = f % 21;
                if (c >= 1) {
                    int cc = c - 1;
                    float y = fmaf(e[j], K2E, -lg[a]);
                    int bin = (int)fmaf(y, 38.2f, 255.4f);
                    bin = max(0, min(255, bin));
                    if (bin > 0) atomicAdd(&h[cc * NBIN + bin], 1);
                    w[a * 5 + (cc >> 2)] |= (unsigned)bin << ((cc & 3) * 8);
                }
            }
        }
#pragma unroll
        for (int a = 0; a < 4; a++) {
            unsigned i = (unsigned)(q * 4 + a);
            *(uint4*)&g_binsP[(size_t)i * 8] =
                make_uint4(w[a * 5], w[a * 5 + 1], w[a * 5 + 2], w[a * 5 + 3]);
            g_binsP[(size_t)i * 8 + 4] = w[a * 5 + 4];
        }
    }
    __syncthreads();
    for (int t = tid; t < NCLS * NBIN; t += 256) {
        int v = h[t];
        if (v) atomicAdd(&g_hist[t], v);
    }
}

// ---------------- K2: widened rank-400 cutoff; then reset state --------------
__global__ void k_cut() {
    int tid = threadIdx.x, wid = tid >> 5, lane = tid & 31;
    for (int c = wid; c < NCLS; c += 8) {
        int cum = 0, cutbin = 1;
        bool found = false;
        for (int base = NBIN - 32; base >= 0; base -= 32) {
            int b = base + 31 - lane;                 // lane 0 = highest bin
            int v = g_hist[c * NBIN + b];
            int s = v;
#pragma unroll
            for (int off = 1; off < 32; off <<= 1) {
                int t = __shfl_up_sync(0xffffffffu, s, off);
                if (lane >= off) s += t;
            }
            unsigned bal = __ballot_sync(0xffffffffu, (cum + s) >= TOPK);
            int tot = __shfl_sync(0xffffffffu, s, 31);
            if (bal) {
                cutbin = base + 31 - (__ffs(bal) - 1);
                found = true;
                break;
            }
            cum += tot;
        }
        if (lane == 0) g_cut[c] = found ? max(cutbin - 2, 1) : 1;
    }
    __syncthreads();
    // reset state for the NEXT call (and selCnt/qCnt for this call's later stages)
    for (int t = tid; t < NCLS * NBIN; t += 256) g_hist[t] = 0;
    if (tid < NCLS) g_selCnt[tid] = 0;
    if (tid == 0) g_qCnt = 0;
    __syncthreads();
    if (tid < 5) {
        unsigned p = 0;
#pragma unroll
        for (int j = 0; j < 4; j++) {
            int c = tid * 4 + j;
            unsigned cv = (c < NCLS) ? (unsigned)g_cut[c] : 255u;
            p |= (cv & 255u) << (j * 8);
        }
        g_cutPack[tid] = p;
    }
}

// ---------------- K3: streaming scan -> survivor queue -----------------------
__global__ void __launch_bounds__(256) k_scan() {
    __shared__ unsigned cp[5];
    if (threadIdx.x < 5) cp[threadIdx.x] = g_cutPack[threadIdx.x];
    __syncthreads();
    int i = blockIdx.x * 256 + threadIdx.x;
    if (i >= AN) return;
    uint4 b4 = *(const uint4*)&g_binsP[(size_t)i * 8];
    unsigned b5 = g_binsP[(size_t)i * 8 + 4];
    unsigned any = __vsetgeu4(b4.x, cp[0]) | __vsetgeu4(b4.y, cp[1]) |
                   __vsetgeu4(b4.z, cp[2]) | __vsetgeu4(b4.w, cp[3]) |
                   __vsetgeu4(b5, cp[4]);
    if (any) {
        int p = atomicAdd(&g_qCnt, 1);
        g_q[p] = (unsigned)i;
    }
}

// ---------------- K4: exact rescoring of survivors ---------------------------
__global__ void k_exact(const float* __restrict__ logits) {
    __shared__ int scut[NCLS];
    if (threadIdx.x < NCLS) scut[threadIdx.x] = g_cut[threadIdx.x];
    __syncthreads();
    int total = g_qCnt;
    for (int e = blockIdx.x * blockDim.x + threadIdx.x; e < total;
         e += gridDim.x * blockDim.x) {
        unsigned i = g_q[e];
        unsigned wv[5];
        uint4 b4 = *(const uint4*)&g_binsP[(size_t)i * 8];
        wv[0] = b4.x; wv[1] = b4.y; wv[2] = b4.z; wv[3] = b4.w;
        wv[4] = g_binsP[(size_t)i * 8 + 4];

        const float* L = logits + (size_t)i * 21;
        float Lr[21];
#pragma unroll
        for (int c = 0; c < 21; c++) Lr[c] = L[c];
        float m = Lr[0];
#pragma unroll
        for (int c = 1; c < 21; c++) m = fmaxf(m, Lr[c]);
        float S = 0.f;
#pragma unroll
        for (int c = 0; c < 21; c++) S += expf(Lr[c] - m);

#pragma unroll
        for (int c = 0; c < NCLS; c++) {
            int b = (wv[c >> 2] >> ((c & 3) * 8)) & 255;
            if (b < scut[c]) continue;
            float ex = expf(Lr[c + 1] - m) / S;       // exact, matches reference
            if (ex <= 0.01f) continue;
            unsigned long long key =
                ((unsigned long long)__float_as_uint(ex) << 32) | (0xFFFFFFFFu - i);
            int p = atomicAdd(&g_selCnt[c], 1);
            if (p < SEL_CAP) g_sel[c * SEL_CAP + p] = key;
        }
    }
}

// ---------------- bitonic sort (descending) in shared ------------------------
__device__ void bitonic_desc(unsigned long long* buf, int np2) {
    int tid = threadIdx.x, bd = blockDim.x;
    for (int k = 2; k <= np2; k <<= 1) {
        for (int j = k >> 1; j > 0; j >>= 1) {
            for (int t = tid; t < np2; t += bd) {
                int ixj = t ^ j;
                if (ixj > t) {
                    unsigned long long a = buf[t], b = buf[ixj];
                    bool desc = ((t & k) == 0);
                    if ((a < b) == desc) { buf[t] = b; buf[ixj] = a; }
                }
            }
            __syncthreads();
        }
    }
}

// ---------------- K5: sort + decode + row-parallel bitmask NMS + compact -----
__global__ void __launch_bounds__(1024) k_sortnms(const float* __restrict__ reg,
                                                  const float* __restrict__ anc) {
    __shared__ unsigned long long buf[SEL_CAP];        // 32KB (keys; tail reused)
    __shared__ float X1[TOPK], Y1[TOPK], X2[TOPK], Y2[TOPK], AR[TOPK];  // 8KB
    __shared__ unsigned supw[NW];
    unsigned* mask = (unsigned*)(buf + 512);           // overlay: keys live in [0,400)
    int c = blockIdx.x, tid = threadIdx.x, lane = tid & 31;
    int n = min(g_selCnt[c], SEL_CAP);
    int np2 = 2; while (np2 < n) np2 <<= 1;
    for (int t = tid; t < np2; t += blockDim.x)
        buf[t] = (t < n) ? g_sel[c * SEL_CAP + t] : 0ull;
    __syncthreads();
    bitonic_desc(buf, np2);
    int nn = min(n, TOPK);

    for (int t = tid; t < nn; t += blockDim.x) {
        unsigned idx = 0xFFFFFFFFu - (unsigned)(buf[t] & 0xFFFFFFFFull);
        float4 a4 = *(const float4*)(anc + (size_t)idx * 4);
        float4 r4 = *(const float4*)(reg + (size_t)idx * 4);
        float aw = a4.z - a4.x, ah = a4.w - a4.y;
        float acx = a4.x + 0.5f * aw, acy = a4.y + 0.5f * ah;
        float dx = r4.x / 10.0f, dy = r4.y / 10.0f;
        float dw = fminf(r4.z / 5.0f, 4.135166556742356f);
        float dh = fminf(r4.w / 5.0f, 4.135166556742356f);
        float pcx = dx * aw + acx, pcy = dy * ah + acy;
        float pw = expf(dw) * aw, ph = expf(dh) * ah;
        float x1 = fminf(fmaxf(pcx - 0.5f * pw, 0.f), 320.f);
        float y1 = fminf(fmaxf(pcy - 0.5f * ph, 0.f), 320.f);
        float x2 = fminf(fmaxf(pcx + 0.5f * pw, 0.f), 320.f);
        float y2 = fminf(fmaxf(pcy + 0.5f * ph, 0.f), 320.f);
        X1[t] = x1; Y1[t] = y1; X2[t] = x2; Y2[t] = y2;
        AR[t] = (x2 - x1) * (y2 - y1);
    }
    __syncthreads();

    int nw_used = (nn + 31) >> 5;
    if (tid < nn) {
        int i = tid;
        float xi1 = X1[i], yi1 = Y1[i], xi2 = X2[i], yi2 = Y2[i], ai = AR[i];
        for (int w = 0; w < nw_used; w++) {
            unsigned m = 0;
            int jbase = w * 32;
            if (jbase + 31 > i) {
#pragma unroll
                for (int b = 0; b < 32; b++) {
                    int j = jbase + b;
                    if (j > i && j < nn) {               // broadcast LDS (same j all lanes)
                        float lx = fmaxf(xi1, X1[j]), ly = fmaxf(yi1, Y1[j]);
                        float rx = fminf(xi2, X2[j]), ry = fminf(yi2, Y2[j]);
                        float ww = fmaxf(rx - lx, 0.f), hh = fmaxf(ry - ly, 0.f);
                        float inter = ww * hh;
                        float iou = inter / (ai + AR[j] - inter);   // NaN>T==false
                        if (iou > NMS_T) m |= (1u << b);
                    }
                }
            }
            mask[i * NW + w] = m;
        }
    }
    __syncthreads();

    if (tid < 32) {                                    // serial greedy sweep
        unsigned sup = 0;
        for (int i = 0; i < nn; i++) {
            unsigned wi = __shfl_sync(0xffffffff, sup, i >> 5);
            if (!((wi >> (i & 31)) & 1)) {
                if (lane < nw_used) sup |= mask[i * NW + lane];
            }
        }
        if (lane < NW) supw[lane] = sup;
    }
    __syncthreads();

    if (tid < 32) {                                    // compact kept, cap DET
        int outc = 0;
        for (int base = 0; base < nn; base += 32) {
            int i = base + lane;
            bool kept = (i < nn) && !((supw[i >> 5] >> (i & 31)) & 1);
            unsigned bal = __ballot_sync(0xffffffff, kept);
            int pos = outc + __popc(bal & ((1u << lane) - 1));
            if (kept && pos < DET) {
                g_kept[c * DET + pos] = buf[i];
                g_keptBox[c * DET + pos] = make_float4(X1[i], Y1[i], X2[i], Y2[i]);
            }
            outc += __popc(bal);
        }
        if (lane == 0) g_keptCnt[c] = min(outc, DET);
    }
}

// ---------------- K6: parallel merge via global sort of kept entries ---------
// key = score<<32 | (31-class)<<8 | (255-pos): desc sort == (score desc,
// class asc, in-class pos asc) == reference stable argsort order.
__global__ void __launch_bounds__(1024) k_out(float* __restrict__ out, int out_size) {
    __shared__ unsigned long long skeys[SEL_CAP];      // 32KB (4096 >= 20*200)
    __shared__ int cnts[NCLS];
    int tid = threadIdx.x;
    for (int t = tid; t < out_size; t += blockDim.x) out[t] = 0.f;
    if (tid < NCLS) cnts[tid] = g_keptCnt[tid];
    __syncthreads();
    for (int t = tid; t < SEL_CAP; t += blockDim.x) {
        unsigned long long key = 0ull;
        if (t < NCLS * DET) {
            int c = t / DET, pos = t % DET;
            if (pos < cnts[c]) {
                unsigned sb = (unsigned)(g_kept[c * DET + pos] >> 32);
                key = ((unsigned long long)sb << 32) |
                      ((unsigned)(31 - c) << 8) | (unsigned)(255 - pos);
            }
        }
        skeys[t] = key;
    }
    __syncthreads();
    bitonic_desc(skeys, SEL_CAP);

    for (int k = tid; k < DET; k += blockDim.x) {
        unsigned long long key = skeys[k];
        unsigned sb = (unsigned)(key >> 32);
        if (sb == 0) continue;                         // out already zeroed
        unsigned low = (unsigned)(key & 0xFFFFFFFFull);
        int c = 31 - (int)((low >> 8) & 0xFF);
        int pos = 255 - (int)(low & 0xFF);
        float4 bx = g_keptBox[c * DET + pos];
        *(float4*)(out + (size_t)k * 4) = bx;
        out[800 + k]  = __uint_as_float(sb);
        out[1000 + k] = (float)(c + 1);
    }
}

// ---------------- launch ------------------------------------------------------
extern "C" void kernel_launch(void* const* d_in, const int* in_sizes, int n_in,
                              void* d_out, int out_size) {
    const float* logits = (const float*)d_in[0];   // [A,21]
    const float* reg    = (const float*)d_in[1];   // [A,4]
    const float* anc    = (const float*)d_in[2];   // [A,4]
    float* out = (float*)d_out;

    k_prep<<<(AN / 4 + 255) / 256, 256>>>(logits);
    k_cut<<<1, 256>>>();
    k_scan<<<(AN + 255) / 256, 256>>>();
    k_exact<<<128, 128>>>(logits);
    k_sortnms<<<NCLS, 1024>>>(reg, anc);
    k_out<<<1, 1024>>>(out, out_size);
}

// round 8
// speedup vs baseline: 1.9126x; 1.0752x over previous
#include <cuda_runtime.h>
#include <cstdint>

#define AN 200000
#define NCLS 20          // foreground classes (labels 1..20)
#define NBIN 256         // log-domain histogram bins
#define TOPK 400
#define SEL_CAP 4096
#define DET 200
#define NW 13            // ceil(TOPK/32)
#define NMS_T 0.45f
#define K2E 1.44269504088896f

// ---------------- scratch (static device globals; no allocation) -------------
__device__ unsigned           g_binsP[AN * 8];          // 20 bin bytes/anchor, 32B stride
__device__ int                g_hist[NCLS * NBIN];
__device__ int                g_cut[NCLS];              // widened cutoff bin (>=1)
__device__ unsigned           g_cutPack[5];             // cut bytes packed like bins
__device__ unsigned long long g_sel[NCLS * SEL_CAP];    // EXACT keys (scorebits<<32)|(~idx)
__device__ int                g_selCnt[NCLS];
__device__ unsigned long long g_kept[NCLS * DET];       // compacted post-NMS keys
__device__ float4             g_keptBox[NCLS * DET];
__device__ int                g_keptCnt[NCLS];

// ---------------- K1: log-domain bins + block-private histogram --------------
// bin = clamp((int)fmaf(log2(score), 38.2, 255.4), 0, 255); score 0.0099 -> ~1.
__global__ void __launch_bounds__(256) k_prep(const float* __restrict__ logits) {
    __shared__ int h[NCLS * NBIN];                     // 20KB private histogram
    int tid = threadIdx.x;
    for (int t = tid; t < NCLS * NBIN; t += 256) h[t] = 0;
    __syncthreads();

    int q = blockIdx.x * 256 + tid;                    // quad of 4 anchors
    if (q < AN / 4) {
        const float4* src = (const float4*)logits + (size_t)q * 21;  // 84 floats
        float S[4] = {0.f, 0.f, 0.f, 0.f};
#pragma unroll
        for (int k = 0; k < 21; k++) {
            float4 v = src[k];
            S[(4 * k + 0) / 21] += exp2f(v.x * K2E);
            S[(4 * k + 1) / 21] += exp2f(v.y * K2E);
            S[(4 * k + 2) / 21] += exp2f(v.z * K2E);
            S[(4 * k + 3) / 21] += exp2f(v.w * K2E);
        }
        float lg[4];
#pragma unroll
        for (int a = 0; a < 4; a++) lg[a] = __log2f(S[a]);

        unsigned w[20];
#pragma unroll
        for (int t = 0; t < 20; t++) w[t] = 0;
#pragma unroll
        for (int k = 0; k < 21; k++) {
            float4 v = src[k];                          // L1 hit (2nd pass)
            float e[4] = {v.x, v.y, v.z, v.w};
#pragma unroll
            for (int j = 0; j < 4; j++) {
                int f = 4 * k + j, a = f / 21, c = f % 21;
                if (c >= 1) {
                    int cc = c - 1;
                    float y = fmaf(e[j], K2E, -lg[a]);
                    int bin = (int)fmaf(y, 38.2f, 255.4f);
                    bin = max(0, min(255, bin));
                    if (bin > 0) atomicAdd(&h[cc * NBIN + bin], 1);
                    w[a * 5 + (cc >> 2)] |= (unsigned)bin << ((cc & 3) * 8);
                }
            }
        }
#pragma unroll
        for (int a = 0; a < 4; a++) {
            unsigned i = (unsigned)(q * 4 + a);
            *(uint4*)&g_binsP[(size_t)i * 8] =
                make_uint4(w[a * 5], w[a * 5 + 1], w[a * 5 + 2], w[a * 5 + 3]);
            g_binsP[(size_t)i * 8 + 4] = w[a * 5 + 4];
        }
    }
    __syncthreads();
    for (int t = tid; t < NCLS * NBIN; t += 256) {
        int v = h[t];
        if (v) atomicAdd(&g_hist[t], v);
    }
}

// ---------------- K2: widened rank-400 cutoff; then reset state --------------
__global__ void k_cut() {
    int tid = threadIdx.x, wid = tid >> 5, lane = tid & 31;
    for (int c = wid; c < NCLS; c += 8) {
        int cum = 0, cutbin = 1;
        bool found = false;
        for (int base = NBIN - 32; base >= 0; base -= 32) {
            int b = base + 31 - lane;                 // lane 0 = highest bin
            int v = g_hist[c * NBIN + b];
            int s = v;
#pragma unroll
            for (int off = 1; off < 32; off <<= 1) {
                int t = __shfl_up_sync(0xffffffffu, s, off);
                if (lane >= off) s += t;
            }
            unsigned bal = __ballot_sync(0xffffffffu, (cum + s) >= TOPK);
            int tot = __shfl_sync(0xffffffffu, s, 31);
            if (bal) {
                cutbin = base + 31 - (__ffs(bal) - 1);
                found = true;
                break;
            }
            cum += tot;
        }
        // widen by 1 bin: approx-score error (~1e-6) vs bin width (~1.8%) margin
        if (lane == 0) g_cut[c] = found ? max(cutbin - 1, 1) : 1;
    }
    __syncthreads();
    // reset for the NEXT call; selCnt consumed later in THIS call
    for (int t = tid; t < NCLS * NBIN; t += 256) g_hist[t] = 0;
    if (tid < NCLS) g_selCnt[tid] = 0;
    __syncthreads();
    if (tid < 5) {
        unsigned p = 0;
#pragma unroll
        for (int j = 0; j < 4; j++) {
            int c = tid * 4 + j;
            unsigned cv = (c < NCLS) ? (unsigned)g_cut[c] : 255u;
            p |= (cv & 255u) << (j * 8);
        }
        g_cutPack[tid] = p;
    }
}

// ---------------- K3: fused scan + exact rescoring (full parallelism) --------
__global__ void __launch_bounds__(256) k_scanexact(const float* __restrict__ logits) {
    __shared__ unsigned cp[5];
    __shared__ int scut[NCLS];
    if (threadIdx.x < 5) cp[threadIdx.x] = g_cutPack[threadIdx.x];
    if (threadIdx.x < NCLS) scut[threadIdx.x] = g_cut[threadIdx.x];
    __syncthreads();
    int i = blockIdx.x * 256 + threadIdx.x;
    if (i >= AN) return;
    uint4 b4 = *(const uint4*)&g_binsP[(size_t)i * 8];
    unsigned b5 = g_binsP[(size_t)i * 8 + 4];
    unsigned any = __vsetgeu4(b4.x, cp[0]) | __vsetgeu4(b4.y, cp[1]) |
                   __vsetgeu4(b4.z, cp[2]) | __vsetgeu4(b4.w, cp[3]) |
                   __vsetgeu4(b5, cp[4]);
    if (!any) return;

    unsigned wv[5] = {b4.x, b4.y, b4.z, b4.w, b5};
    // exact softmax pieces (accurate expf, div.rn) — matches reference path
    const float* L = logits + (size_t)i * 21;
    float Lr[21];
#pragma unroll
    for (int c = 0; c < 21; c++) Lr[c] = L[c];
    float m = Lr[0];
#pragma unroll
    for (int c = 1; c < 21; c++) m = fmaxf(m, Lr[c]);
    float S = 0.f;
#pragma unroll
    for (int c = 0; c < 21; c++) S += expf(Lr[c] - m);

#pragma unroll
    for (int c = 0; c < NCLS; c++) {
        int b = (wv[c >> 2] >> ((c & 3) * 8)) & 255;
        if (b < scut[c]) continue;
        float ex = expf(Lr[c + 1] - m) / S;            // exact, matches reference
        if (ex <= 0.01f) continue;
        unsigned long long key =
            ((unsigned long long)__float_as_uint(ex) << 32) | (0xFFFFFFFFu - (unsigned)i);
        int p = atomicAdd(&g_selCnt[c], 1);
        if (p < SEL_CAP) g_sel[c * SEL_CAP + p] = key;
    }
}

// ---------------- bitonic sort (descending) in shared ------------------------
__device__ void bitonic_desc(unsigned long long* buf, int np2) {
    int tid = threadIdx.x, bd = blockDim.x;
    for (int k = 2; k <= np2; k <<= 1) {
        for (int j = k >> 1; j > 0; j >>= 1) {
            for (int t = tid; t < np2; t += bd) {
                int ixj = t ^ j;
                if (ixj > t) {
                    unsigned long long a = buf[t], b = buf[ixj];
                    bool desc = ((t & k) == 0);
                    if ((a < b) == desc) { buf[t] = b; buf[ixj] = a; }
                }
            }
            __syncthreads();
        }
    }
}

// ---------------- K4: sort + decode + row-parallel bitmask NMS + compact -----
__global__ void __launch_bounds__(1024) k_sortnms(const float* __restrict__ reg,
                                                  const float* __restrict__ anc) {
    __shared__ unsigned long long buf[SEL_CAP];        // 32KB (keys; tail reused)
    __shared__ float X1[TOPK], Y1[TOPK], X2[TOPK], Y2[TOPK], AR[TOPK];  // 8KB
    __shared__ unsigned supw[NW];
    unsigned* mask = (unsigned*)(buf + 512);           // overlay: keys live in [0,400)
    int c = blockIdx.x, tid = threadIdx.x, lane = tid & 31;
    int n = min(g_selCnt[c], SEL_CAP);
    int np2 = 2; while (np2 < n) np2 <<= 1;
    for (int t = tid; t < np2; t += blockDim.x)
        buf[t] = (t < n) ? g_sel[c * SEL_CAP + t] : 0ull;
    __syncthreads();
    bitonic_desc(buf, np2);
    int nn = min(n, TOPK);

    for (int t = tid; t < nn; t += blockDim.x) {
        unsigned idx = 0xFFFFFFFFu - (unsigned)(buf[t] & 0xFFFFFFFFull);
        float4 a4 = *(const float4*)(anc + (size_t)idx * 4);
        float4 r4 = *(const float4*)(reg + (size_t)idx * 4);
        float aw = a4.z - a4.x, ah = a4.w - a4.y;
        float acx = a4.x + 0.5f * aw, acy = a4.y + 0.5f * ah;
        float dx = r4.x / 10.0f, dy = r4.y / 10.0f;
        float dw = fminf(r4.z / 5.0f, 4.135166556742356f);
        float dh = fminf(r4.w / 5.0f, 4.135166556742356f);
        float pcx = dx * aw + acx, pcy = dy * ah + acy;
        float pw = expf(dw) * aw, ph = expf(dh) * ah;
        float x1 = fminf(fmaxf(pcx - 0.5f * pw, 0.f), 320.f);
        float y1 = fminf(fmaxf(pcy - 0.5f * ph, 0.f), 320.f);
        float x2 = fminf(fmaxf(pcx + 0.5f * pw, 0.f), 320.f);
        float y2 = fminf(fmaxf(pcy + 0.5f * ph, 0.f), 320.f);
        X1[t] = x1; Y1[t] = y1; X2[t] = x2; Y2[t] = y2;
        AR[t] = (x2 - x1) * (y2 - y1);
    }
    __syncthreads();

    int nw_used = (nn + 31) >> 5;
    if (tid < nn) {
        int i = tid;
        float xi1 = X1[i], yi1 = Y1[i], xi2 = X2[i], yi2 = Y2[i], ai = AR[i];
        for (int w = 0; w < nw_used; w++) {
            unsigned m = 0;
            int jbase = w * 32;
            if (jbase + 31 > i) {
#pragma unroll
                for (int b = 0; b < 32; b++) {
                    int j = jbase + b;
                    if (j > i && j < nn) {               // broadcast LDS (same j all lanes)
                        float lx = fmaxf(xi1, X1[j]), ly = fmaxf(yi1, Y1[j]);
                        float rx = fminf(xi2, X2[j]), ry = fminf(yi2, Y2[j]);
                        float ww = fmaxf(rx - lx, 0.f), hh = fmaxf(ry - ly, 0.f);
                        float inter = ww * hh;
                        float iou = inter / (ai + AR[j] - inter);   // NaN>T==false
                        if (iou > NMS_T) m |= (1u << b);
                    }
                }
            }
            mask[i * NW + w] = m;
        }
    }
    __syncthreads();

    if (tid < 32) {                                    // serial greedy sweep, prefetched
        unsigned sup = 0;
        bool act = (lane < nw_used);
        unsigned cur = (act && nn > 0) ? mask[lane] : 0u;
        for (int i = 0; i < nn; i++) {
            unsigned nxt = (act && i + 1 < nn) ? mask[(i + 1) * NW + lane] : 0u;
            unsigned wi = __shfl_sync(0xffffffff, sup, i >> 5);
            if (!((wi >> (i & 31)) & 1)) sup |= cur;
            cur = nxt;
        }
        if (lane < NW) supw[lane] = sup;
    }
    __syncthreads();

    if (tid < 32) {                                    // compact kept, cap DET
        int outc = 0;
        for (int base = 0; base < nn; base += 32) {
            int i = base + lane;
            bool kept = (i < nn) && !((supw[i >> 5] >> (i & 31)) & 1);
            unsigned bal = __ballot_sync(0xffffffff, kept);
            int pos = outc + __popc(bal & ((1u << lane) - 1));
            if (kept && pos < DET) {
                g_kept[c * DET + pos] = buf[i];
                g_keptBox[c * DET + pos] = make_float4(X1[i], Y1[i], X2[i], Y2[i]);
            }
            outc += __popc(bal);
        }
        if (lane == 0) g_keptCnt[c] = min(outc, DET);
    }
}

// ---------------- K5: parallel merge via sort of kept entries ----------------
// key = score<<32 | (31-class)<<8 | (255-pos): desc sort == (score desc,
// class asc, in-class pos asc) == reference stable argsort order.
__global__ void __launch_bounds__(1024) k_out(float* __restrict__ out, int out_size) {
    __shared__ unsigned long long skeys[SEL_CAP];      // 32KB (4096 >= 20*200)
    __shared__ int cnts[NCLS];
    int tid = threadIdx.x;
    for (int t = tid; t < out_size; t += blockDim.x) out[t] = 0.f;
    if (tid < NCLS) cnts[tid] = g_keptCnt[tid];
    __syncthreads();
    for (int t = tid; t < SEL_CAP; t += blockDim.x) {
        unsigned long long key = 0ull;
        if (t < NCLS * DET) {
            int c = t / DET, pos = t % DET;
            if (pos < cnts[c]) {
                unsigned sb = (unsigned)(g_kept[c * DET + pos] >> 32);
                key = ((unsigned long long)sb << 32) |
                      ((unsigned)(31 - c) << 8) | (unsigned)(255 - pos);
            }
        }
        skeys[t] = key;
    }
    __syncthreads();
    bitonic_desc(skeys, SEL_CAP);

    for (int k = tid; k < DET; k += blockDim.x) {
        unsigned long long key = skeys[k];
        unsigned sb = (unsigned)(key >> 32);
        if (sb == 0) continue;                         // out already zeroed
        unsigned low = (unsigned)(key & 0xFFFFFFFFull);
        int c = 31 - (int)((low >> 8) & 0xFF);
        int pos = 255 - (int)(low & 0xFF);
        float4 bx = g_keptBox[c * DET + pos];
        *(float4*)(out + (size_t)k * 4) = bx;
        out[800 + k]  = __uint_as_float(sb);
        out[1000 + k] = (float)(c + 1);
    }
}

// ---------------- launch ------------------------------------------------------
extern "C" void kernel_launch(void* const* d_in, const int* in_sizes, int n_in,
                              void* d_out, int out_size) {
    const float* logits = (const float*)d_in[0];   // [A,21]
    const float* reg    = (const float*)d_in[1];   // [A,4]
    const float* anc    = (const float*)d_in[2];   // [A,4]
    float* out = (float*)d_out;

    k_prep<<<(AN / 4 + 255) / 256, 256>>>(logits);
    k_cut<<<1, 256>>>();
    k_scanexact<<<(AN + 255) / 256, 256>>>(logits);
    k_sortnms<<<NCLS, 1024>>>(reg, anc);           // launch #4 -> ncu target
    k_out<<<1, 1024>>>(out, out_size);
}